// round 6
// baseline (speedup 1.0000x reference)
#include <cuda_runtime.h>
#include <cuda_bf16.h>
#include <cstdint>
#include <math.h>

#define BB 2
#define SS 1024
#define DD 768
#define HH 12
#define DK 64
#define FF 3072
#define LL 4
#define VV 32000
#define MTOK (BB*SS)   /* 2048 */

typedef __nv_bfloat16 bf16;

// ---------------- scratch ----------------------------------------------------
__device__ float g_h  [MTOK*DD];
__device__ int   g_xi [MTOK];

__device__ bf16 g_tok_hi[VV*DD],    g_tok_lo[VV*DD];
__device__ bf16 g_wq_hi [LL*DD*DD], g_wq_lo [LL*DD*DD];
__device__ bf16 g_wk_hi [LL*DD*DD], g_wk_lo [LL*DD*DD];
__device__ bf16 g_wv_hi [LL*DD*DD], g_wv_lo [LL*DD*DD];
__device__ bf16 g_wo_hi [LL*DD*DD], g_wo_lo [LL*DD*DD];
__device__ bf16 g_w1_hi [LL*FF*DD], g_w1_lo [LL*FF*DD];
__device__ bf16 g_w2_hi [LL*DD*FF], g_w2_lo [LL*DD*FF];
__device__ bf16 g_a_hi  [MTOK*DD],  g_a_lo  [MTOK*DD];
__device__ bf16 g_f_hi  [MTOK*FF],  g_f_lo  [MTOK*FF];
__device__ bf16 g_qh[MTOK*DD], g_ql[MTOK*DD];
__device__ bf16 g_kh[MTOK*DD], g_kl[MTOK*DD];
__device__ bf16 g_vh[MTOK*DD], g_vl[MTOK*DD];

// ---------------- helpers ----------------------------------------------------
__device__ __forceinline__ uint32_t smem_u32(const void* p) {
    uint32_t a;
    asm("{ .reg .u64 t; cvta.to.shared.u64 t, %1; cvt.u32.u64 %0, t; }" : "=r"(a) : "l"(p));
    return a;
}
__device__ __forceinline__ void cpasync16(uint32_t saddr, const void* gaddr) {
    asm volatile("cp.async.cg.shared.global [%0], [%1], 16;" :: "r"(saddr), "l"(gaddr));
}
#define CP_COMMIT() asm volatile("cp.async.commit_group;" ::: "memory")
#define CP_WAIT(N)  asm volatile("cp.async.wait_group %0;" :: "n"(N) : "memory")

__device__ __forceinline__ void ldsm4(uint32_t* r, uint32_t addr) {
    asm volatile("ldmatrix.sync.aligned.m8n8.x4.shared.b16 {%0,%1,%2,%3}, [%4];"
        : "=r"(r[0]), "=r"(r[1]), "=r"(r[2]), "=r"(r[3]) : "r"(addr));
}
__device__ __forceinline__ void ldsm4t(uint32_t* r, uint32_t addr) {
    asm volatile("ldmatrix.sync.aligned.m8n8.x4.trans.shared.b16 {%0,%1,%2,%3}, [%4];"
        : "=r"(r[0]), "=r"(r[1]), "=r"(r[2]), "=r"(r[3]) : "r"(addr));
}
__device__ __forceinline__ void mma16816(float* c, const uint32_t* a, const uint32_t* b) {
    asm volatile(
        "mma.sync.aligned.m16n8k16.row.col.f32.bf16.bf16.f32 "
        "{%0,%1,%2,%3}, {%4,%5,%6,%7}, {%8,%9}, {%0,%1,%2,%3};"
        : "+f"(c[0]), "+f"(c[1]), "+f"(c[2]), "+f"(c[3])
        : "r"(a[0]), "r"(a[1]), "r"(a[2]), "r"(a[3]), "r"(b[0]), "r"(b[1]));
}
__device__ __forceinline__ void split1(float v, bf16& h, bf16& l) {
    h = __float2bfloat16(v);
    l = __float2bfloat16(v - __bfloat162float(h));
}
__device__ __forceinline__ uint32_t packbf(float v0, float v1) {
    __nv_bfloat162 p(__float2bfloat16(v0), __float2bfloat16(v1));
    return *(uint32_t*)&p;
}

// ---------------- token ids / embed ------------------------------------------
__global__ void cvt_x_kernel(const long long* __restrict__ x64) {
    __shared__ int is64;
    if (threadIdx.x == 0) {
        int ok = 1;
        for (int i = 0; i < 16; i++) { long long t = x64[i]; if (t < 0 || t >= VV) ok = 0; }
        is64 = ok;
    }
    __syncthreads();
    const int* x32 = (const int*)x64;
    if (is64) for (int i = threadIdx.x; i < MTOK; i += blockDim.x) g_xi[i] = (int)x64[i];
    else      for (int i = threadIdx.x; i < MTOK; i += blockDim.x) g_xi[i] = x32[i];
}

__global__ void embed_kernel(const float* __restrict__ tok, const float* __restrict__ pos) {
    int idx = blockIdx.x * blockDim.x + threadIdx.x;
    if (idx < MTOK * DD) {
        int d = idx % DD, t = idx / DD, s = t % SS;
        g_h[idx] = tok[g_xi[t] * DD + d] + pos[s * DD + d];
    }
}

// ---------------- layernorm -> bf16 hi/lo ------------------------------------
__global__ void ln_kernel(const float* __restrict__ in, const float* __restrict__ g,
                          const float* __restrict__ b,
                          bf16* __restrict__ ohi, bf16* __restrict__ olo) {
    int row = blockIdx.x, tid = threadIdx.x;
    const float* xr = in + (size_t)row * DD;
    __shared__ float r1[256], r2[256];
    float s1 = 0.f, s2 = 0.f;
    for (int i = tid; i < DD; i += 256) { float v = xr[i]; s1 += v; s2 += v * v; }
    r1[tid] = s1; r2[tid] = s2;
    __syncthreads();
    for (int o = 128; o > 0; o >>= 1) {
        if (tid < o) { r1[tid] += r1[tid + o]; r2[tid] += r2[tid + o]; }
        __syncthreads();
    }
    float mu = r1[0] * (1.0f / DD);
    float var = r2[0] * (1.0f / DD) - mu * mu;
    float inv = rsqrtf(var + 1e-5f);
    for (int i = tid; i < DD; i += 256) {
        float v = (xr[i] - mu) * inv * g[i] + b[i];
        bf16 h, l; split1(v, h, l);
        ohi[(size_t)row * DD + i] = h;
        olo[(size_t)row * DD + i] = l;
    }
}

// ---------------- fp32 -> bf16 hi/lo splits ----------------------------------
__device__ __forceinline__ void split4_body(const float4* x, __nv_bfloat162* hi,
                                            __nv_bfloat162* lo, int i) {
    float4 v = x[i];
    bf16 hx, lx, hy, ly, hz, lz, hw, lw;
    split1(v.x, hx, lx); split1(v.y, hy, ly);
    split1(v.z, hz, lz); split1(v.w, hw, lw);
    hi[2*i]   = __nv_bfloat162(hx, hy);
    hi[2*i+1] = __nv_bfloat162(hz, hw);
    lo[2*i]   = __nv_bfloat162(lx, ly);
    lo[2*i+1] = __nv_bfloat162(lz, lw);
}

__global__ void split_kernel(const float4* __restrict__ x,
                             __nv_bfloat162* __restrict__ hi,
                             __nv_bfloat162* __restrict__ lo, int n4) {
    int i = blockIdx.x * blockDim.x + threadIdx.x;
    if (i < n4) split4_body(x, hi, lo, i);
}

// all 6 weight tensors in one launch (grid.y selects the tensor)
__global__ void split_w_kernel(
        const float4* s0, __nv_bfloat162* h0, __nv_bfloat162* l0, int n0,
        const float4* s1, __nv_bfloat162* h1, __nv_bfloat162* l1, int n1,
        const float4* s2, __nv_bfloat162* h2, __nv_bfloat162* l2, int n2,
        const float4* s3, __nv_bfloat162* h3, __nv_bfloat162* l3, int n3,
        const float4* s4, __nv_bfloat162* h4, __nv_bfloat162* l4, int n4_,
        const float4* s5, __nv_bfloat162* h5, __nv_bfloat162* l5, int n5) {
    const float4* s; __nv_bfloat162* h; __nv_bfloat162* l; int n;
    switch (blockIdx.y) {
        case 0: s = s0; h = h0; l = l0; n = n0; break;
        case 1: s = s1; h = h1; l = l1; n = n1; break;
        case 2: s = s2; h = h2; l = l2; n = n2; break;
        case 3: s = s3; h = h3; l = l3; n = n3; break;
        case 4: s = s4; h = h4; l = l4; n = n4_; break;
        default: s = s5; h = h5; l = l5; n = n5; break;
    }
    int i = blockIdx.x * blockDim.x + threadIdx.x;
    if (i < n) split4_body(s, h, l, i);
}

// ---------------- split-bf16 mma.sync GEMM core ------------------------------
#define PADE   40
#define TILEB  (128*PADE*2)

// EPI: 0 f32+bias, 1 f32+bias+res, 2 bf16split+bias+relu, 3 f32, 4 bf16split+bias+scale
template<int EPI, int MT>
__device__ __forceinline__ void gemm_core(
        const bf16* Ahi, const bf16* Alo, const bf16* Bhi, const bf16* Blo,
        const float* bias, const float* res, float sc,
        float* C, bf16* Chi, bf16* Clo,
        int m0, int n0, int N, int K, uint32_t sb) {
    constexpr int MF = MT / 32;                   // 4 (MT=128) or 2 (MT=64)
    constexpr int ATB = MT * PADE * 2;            // A tile bytes
    constexpr int STB = 2 * ATB + 2 * TILEB;      // stage bytes
    const int tid = threadIdx.x;
    const int wid = tid >> 5, lane = tid & 31;
    const int wm = (wid >> 2) * (MT / 2);
    const int wn = (wid & 3) * 32;

    float Cf[MF][4][4];
#pragma unroll
    for (int i = 0; i < MF; i++)
#pragma unroll
        for (int j = 0; j < 4; j++)
#pragma unroll
            for (int x = 0; x < 4; x++) Cf[i][j][x] = 0.f;

    const int NS = K >> 5;
    const int a_row = (lane & 15);
    const int a_colsel = (lane >> 4) * 8;
    const int b_row = (lane & 7) + ((lane >> 4) & 1) * 8;
    const int b_colsel = ((lane >> 3) & 1) * 8;
    const int lr = tid >> 2;           // 0..63
    const int lc = tid & 3;

    // ---- stage loader (lambda-free, inline twice) ----
#define LOAD_STAGE(SB_, K0_)                                                    \
    do {                                                                        \
        uint32_t tb = (SB_);                                                    \
        _Pragma("unroll")                                                       \
        for (int hr = 0; hr < MT / 64; hr++) {                                  \
            int row = lr + hr * 64;                                             \
            cpasync16(tb + row * (PADE*2) + lc * 16,                            \
                      Ahi + (size_t)(m0 + row) * K + (K0_) + lc * 8);           \
            cpasync16(tb + ATB + row * (PADE*2) + lc * 16,                      \
                      Alo + (size_t)(m0 + row) * K + (K0_) + lc * 8);           \
        }                                                                       \
        _Pragma("unroll")                                                       \
        for (int hr = 0; hr < 2; hr++) {                                        \
            int row = lr + hr * 64;                                             \
            cpasync16(tb + 2*ATB + row * (PADE*2) + lc * 16,                    \
                      Bhi + (size_t)(n0 + row) * K + (K0_) + lc * 8);           \
            cpasync16(tb + 2*ATB + TILEB + row * (PADE*2) + lc * 16,            \
                      Blo + (size_t)(n0 + row) * K + (K0_) + lc * 8);           \
        }                                                                       \
    } while (0)

    LOAD_STAGE(sb, 0);
    CP_COMMIT();

    for (int s = 0; s < NS; s++) {
        if (s + 1 < NS) {
            LOAD_STAGE(sb + ((s + 1) & 1) * STB, (s + 1) << 5);
            CP_COMMIT();
            CP_WAIT(1);
        } else {
            CP_WAIT(0);
        }
        __syncthreads();

        const uint32_t st = sb + (s & 1) * STB;
        const uint32_t tAh = st;
        const uint32_t tAl = st + ATB;
        const uint32_t tBh = st + 2 * ATB;
        const uint32_t tBl = st + 2 * ATB + TILEB;

#pragma unroll
        for (int k16 = 0; k16 < 32; k16 += 16) {
            uint32_t Aany[MF][4], Bh[2][4], Bl[2][4];
#pragma unroll
            for (int mf = 0; mf < MF; mf++)
                ldsm4(Aany[mf], tAh + (wm + mf * 16 + a_row) * (PADE*2) + (k16 + a_colsel) * 2);
#pragma unroll
            for (int p = 0; p < 2; p++) {
                ldsm4(Bh[p], tBh + (wn + p * 16 + b_row) * (PADE*2) + (k16 + b_colsel) * 2);
                ldsm4(Bl[p], tBl + (wn + p * 16 + b_row) * (PADE*2) + (k16 + b_colsel) * 2);
            }
            // pass 1: Ahi*Bhi
#pragma unroll
            for (int mf = 0; mf < MF; mf++)
#pragma unroll
                for (int nf = 0; nf < 4; nf++)
                    mma16816(Cf[mf][nf], Aany[mf], &Bh[nf >> 1][(nf & 1) * 2]);
            // pass 2: Ahi*Blo
#pragma unroll
            for (int mf = 0; mf < MF; mf++)
#pragma unroll
                for (int nf = 0; nf < 4; nf++)
                    mma16816(Cf[mf][nf], Aany[mf], &Bl[nf >> 1][(nf & 1) * 2]);
            // pass 3: Alo*Bhi (Bh cached in regs)
#pragma unroll
            for (int mf = 0; mf < MF; mf++)
                ldsm4(Aany[mf], tAl + (wm + mf * 16 + a_row) * (PADE*2) + (k16 + a_colsel) * 2);
#pragma unroll
            for (int mf = 0; mf < MF; mf++)
#pragma unroll
                for (int nf = 0; nf < 4; nf++)
                    mma16816(Cf[mf][nf], Aany[mf], &Bh[nf >> 1][(nf & 1) * 2]);
        }
        __syncthreads();
    }
#undef LOAD_STAGE

    const int g = lane >> 2, t2 = (lane & 3) * 2;
#pragma unroll
    for (int mf = 0; mf < MF; mf++) {
#pragma unroll
        for (int nf = 0; nf < 4; nf++) {
            int n = n0 + wn + nf * 8 + t2;
#pragma unroll
            for (int hrow = 0; hrow < 2; hrow++) {
                int m = m0 + wm + mf * 16 + g + hrow * 8;
                float v0 = Cf[mf][nf][hrow * 2 + 0];
                float v1 = Cf[mf][nf][hrow * 2 + 1];
                if (EPI != 3) { v0 += bias[n]; v1 += bias[n + 1]; }
                if (EPI == 2 || EPI == 4) {
                    if (EPI == 2) { v0 = fmaxf(v0, 0.f); v1 = fmaxf(v1, 0.f); }
                    else          { v0 *= sc; v1 *= sc; }
                    bf16 h0, l0, h1, l1;
                    split1(v0, h0, l0); split1(v1, h1, l1);
                    *(__nv_bfloat162*)&Chi[(size_t)m * N + n] = __nv_bfloat162(h0, h1);
                    *(__nv_bfloat162*)&Clo[(size_t)m * N + n] = __nv_bfloat162(l0, l1);
                } else {
                    if (EPI == 1) {
                        const float2 rr = *(const float2*)&res[(size_t)m * N + n];
                        v0 += rr.x; v1 += rr.y;
                    }
                    *(float2*)&C[(size_t)m * N + n] = make_float2(v0, v1);
                }
            }
        }
    }
}

#define GSMEM128 (2*(2*128*PADE*2 + 2*TILEB))   /* 81920 */
#define GSMEM64  (2*(2*64*PADE*2  + 2*TILEB))   /* 61440 */

template<int EPI>
__global__ __launch_bounds__(256, 2)
void mm_gemm128(const bf16* __restrict__ Ahi, const bf16* __restrict__ Alo,
                const bf16* __restrict__ Bhi, const bf16* __restrict__ Blo,
                const float* __restrict__ bias, const float* __restrict__ res,
                float* __restrict__ C, bf16* __restrict__ Chi, bf16* __restrict__ Clo,
                int N, int K) {
    extern __shared__ char smem_raw[];
    gemm_core<EPI, 128>(Ahi, Alo, Bhi, Blo, bias, res, 1.0f, C, Chi, Clo,
                        blockIdx.y * 128, blockIdx.x * 128, N, K, smem_u32(smem_raw));
}

template<int EPI>
__global__ __launch_bounds__(256, 3)
void mm_gemm64(const bf16* __restrict__ Ahi, const bf16* __restrict__ Alo,
               const bf16* __restrict__ Bhi, const bf16* __restrict__ Blo,
               const float* __restrict__ bias, const float* __restrict__ res,
               float* __restrict__ C, bf16* __restrict__ Chi, bf16* __restrict__ Clo,
               int N, int K) {
    extern __shared__ char smem_raw[];
    gemm_core<EPI, 64>(Ahi, Alo, Bhi, Blo, bias, res, 1.0f, C, Chi, Clo,
                       blockIdx.y * 64, blockIdx.x * 128, N, K, smem_u32(smem_raw));
}

// fused QKV -> bf16 hi/lo outputs; q scaled by 1/8
__global__ __launch_bounds__(256, 2)
void qkv_gemm(const bf16* __restrict__ Ahi, const bf16* __restrict__ Alo,
              const bf16* __restrict__ wqh, const bf16* __restrict__ wql,
              const bf16* __restrict__ wkh, const bf16* __restrict__ wkl,
              const bf16* __restrict__ wvh, const bf16* __restrict__ wvl,
              const float* __restrict__ bq, const float* __restrict__ bk,
              const float* __restrict__ bv,
              bf16* __restrict__ qh, bf16* __restrict__ ql,
              bf16* __restrict__ kh, bf16* __restrict__ kl,
              bf16* __restrict__ vh, bf16* __restrict__ vl) {
    extern __shared__ char smem_raw[];
    const int which = blockIdx.x / 6, nb = blockIdx.x % 6;
    const bf16* Bh = (which == 0) ? wqh : (which == 1) ? wkh : wvh;
    const bf16* Bl = (which == 0) ? wql : (which == 1) ? wkl : wvl;
    const float* bias = (which == 0) ? bq : (which == 1) ? bk : bv;
    bf16* Ch = (which == 0) ? qh : (which == 1) ? kh : vh;
    bf16* Cl = (which == 0) ? ql : (which == 1) ? kl : vl;
    float sc = (which == 0) ? 0.125f : 1.0f;
    gemm_core<4, 128>(Ahi, Alo, Bh, Bl, bias, nullptr, sc, nullptr, Ch, Cl,
                      blockIdx.y * 128, nb * 128, DD, DD, smem_u32(smem_raw));
}

// ---------------- MMA flash attention ---------------------------------------
#define AST 144
#define ATILE (64*AST)
#define ATT_SMEM (2*ATILE + 2*4*ATILE)

__device__ __forceinline__ void att_load4(uint32_t dst, const bf16* src,
                                          size_t grow0, int hcol, int tid) {
    int r = tid >> 1, c0 = (tid & 1) * 4;
    const bf16* p = src + (grow0 + r) * DD + hcol + c0 * 8;
    uint32_t d = dst + r * AST + c0 * 16;
#pragma unroll
    for (int i = 0; i < 4; i++) cpasync16(d + i * 16, p + i * 8);
}

__global__ __launch_bounds__(128)
void flash_attn(const bf16* __restrict__ qh, const bf16* __restrict__ ql,
                const bf16* __restrict__ kh, const bf16* __restrict__ kl,
                const bf16* __restrict__ vh, const bf16* __restrict__ vl,
                bf16* __restrict__ chi, bf16* __restrict__ clo) {
    const int qt = gridDim.x - 1 - blockIdx.x;
    const int hd = blockIdx.y, b = blockIdx.z;
    extern __shared__ char smc[];
    const uint32_t sb = smem_u32(smc);
    const uint32_t Qh_s = sb, Ql_s = sb + ATILE;
    const uint32_t KV = sb + 2 * ATILE;

    const int tid = threadIdx.x, wid = tid >> 5, lane = tid & 31;
    const size_t qrow0 = (size_t)(b * SS + qt * 64);
    const int hcol = hd * DK;

    att_load4(Qh_s, qh, qrow0, hcol, tid);
    att_load4(Ql_s, ql, qrow0, hcol, tid);
    {
        size_t kr = (size_t)(b * SS);
        att_load4(KV + 0 * ATILE, kh, kr, hcol, tid);
        att_load4(KV + 1 * ATILE, kl, kr, hcol, tid);
        att_load4(KV + 2 * ATILE, vh, kr, hcol, tid);
        att_load4(KV + 3 * ATILE, vl, kr, hcol, tid);
    }
    CP_COMMIT();

    float O[8][4];
    float mrow[2] = { -1e30f, -1e30f };
    float lrow[2] = { 0.f, 0.f };
#pragma unroll
    for (int nt = 0; nt < 8; nt++)
#pragma unroll
        for (int x = 0; x < 4; x++) O[nt][x] = 0.f;

    const int g = lane >> 2, t2q = (lane & 3) * 2;
    const int a_row = wid * 16 + (lane & 15);
    const uint32_t a_cs = ((lane >> 4) << 3) * 2;
    const int b_row = (lane & 7) + (((lane >> 4) & 1) << 3);
    const uint32_t b_cs = (((lane >> 3) & 1) << 3) * 2;
    const int v_row = (lane & 15);
    const uint32_t v_cs = ((lane >> 4) << 3) * 2;

    for (int jt = 0; jt <= qt; jt++) {
        if (jt < qt) {
            size_t kr = (size_t)(b * SS + (jt + 1) * 64);
            uint32_t nb = KV + ((jt + 1) & 1) * (4 * ATILE);
            att_load4(nb + 0 * ATILE, kh, kr, hcol, tid);
            att_load4(nb + 1 * ATILE, kl, kr, hcol, tid);
            att_load4(nb + 2 * ATILE, vh, kr, hcol, tid);
            att_load4(nb + 3 * ATILE, vl, kr, hcol, tid);
            CP_COMMIT();
            CP_WAIT(1);
        } else {
            CP_WAIT(0);
        }
        __syncthreads();

        const uint32_t Kh_s = KV + (jt & 1) * (4 * ATILE);
        const uint32_t Kl_s = Kh_s + ATILE;
        const uint32_t Vh_s = Kl_s + ATILE;
        const uint32_t Vl_s = Vh_s + ATILE;

        float S[8][4];
#pragma unroll
        for (int nt = 0; nt < 8; nt++)
#pragma unroll
            for (int x = 0; x < 4; x++) S[nt][x] = 0.f;

#pragma unroll
        for (int ks = 0; ks < 4; ks++) {
            uint32_t Ah[4], Al[4];
            ldsm4(Ah, Qh_s + a_row * AST + ks * 32 + a_cs);
            ldsm4(Al, Ql_s + a_row * AST + ks * 32 + a_cs);
#pragma unroll
            for (int p = 0; p < 2; p++) {
                uint32_t Bh4[4], Bl4[4];
                ldsm4(Bh4, Kh_s + (p * 16 + b_row) * AST + ks * 32 + b_cs);
                ldsm4(Bl4, Kl_s + (p * 16 + b_row) * AST + ks * 32 + b_cs);
#pragma unroll
                for (int q = 0; q < 2; q++) {
                    mma16816(S[p * 2 + q], Ah, &Bh4[q * 2]);
                    mma16816(S[p * 2 + q], Ah, &Bl4[q * 2]);
                    mma16816(S[p * 2 + q], Al, &Bh4[q * 2]);
                }
                uint32_t Bh4b[4], Bl4b[4];
                ldsm4(Bh4b, Kh_s + ((p + 2) * 16 + b_row) * AST + ks * 32 + b_cs);
                ldsm4(Bl4b, Kl_s + ((p + 2) * 16 + b_row) * AST + ks * 32 + b_cs);
#pragma unroll
                for (int q = 0; q < 2; q++) {
                    mma16816(S[(p + 2) * 2 + q], Ah, &Bh4b[q * 2]);
                    mma16816(S[(p + 2) * 2 + q], Ah, &Bl4b[q * 2]);
                    mma16816(S[(p + 2) * 2 + q], Al, &Bh4b[q * 2]);
                }
            }
        }

        const bool diag = (jt == qt);
#pragma unroll
        for (int half = 0; half < 2; half++) {
            const int rloc = wid * 16 + g + half * 8;
            float mt = -1e30f;
#pragma unroll
            for (int nt = 0; nt < 8; nt++) {
                float s0 = S[nt][half * 2], s1 = S[nt][half * 2 + 1];
                if (diag) {
                    if (nt * 8 + t2q > rloc)     s0 = -1e30f;
                    if (nt * 8 + t2q + 1 > rloc) s1 = -1e30f;
                }
                S[nt][half * 2] = s0; S[nt][half * 2 + 1] = s1;
                mt = fmaxf(mt, fmaxf(s0, s1));
            }
            mt = fmaxf(mt, __shfl_xor_sync(0xffffffffu, mt, 1));
            mt = fmaxf(mt, __shfl_xor_sync(0xffffffffu, mt, 2));
            float mn = fmaxf(mrow[half], mt);
            float f = __expf(mrow[half] - mn);
            mrow[half] = mn;
            float rs = 0.f;
#pragma unroll
            for (int nt = 0; nt < 8; nt++) {
                float e0 = __expf(S[nt][half * 2] - mn);
                float e1 = __expf(S[nt][half * 2 + 1] - mn);
                S[nt][half * 2] = e0; S[nt][half * 2 + 1] = e1;
                rs += e0 + e1;
            }
            rs += __shfl_xor_sync(0xffffffffu, rs, 1);
            rs += __shfl_xor_sync(0xffffffffu, rs, 2);
            lrow[half] = lrow[half] * f + rs;
#pragma unroll
            for (int nt = 0; nt < 8; nt++) {
                O[nt][half * 2] *= f; O[nt][half * 2 + 1] *= f;
            }
        }

#pragma unroll
        for (int ks = 0; ks < 4; ks++) {
            uint32_t Ph[4], Pl[4];
#pragma unroll
            for (int q4 = 0; q4 < 4; q4++) {
                int tile = 2 * ks + (q4 >> 1);
                int o = (q4 & 1) * 2;
                float v0 = S[tile][o], v1 = S[tile][o + 1];
                bf16 h0 = __float2bfloat16(v0), h1 = __float2bfloat16(v1);
                __nv_bfloat162 hh(h0, h1);
                Ph[q4] = *(uint32_t*)&hh;
                Pl[q4] = packbf(v0 - __bfloat162float(h0), v1 - __bfloat162float(h1));
            }
#pragma unroll
            for (int nt = 0; nt < 4; nt++) {
                uint32_t Vh4[4], Vl4[4];
                ldsm4t(Vh4, Vh_s + (ks * 16 + v_row) * AST + nt * 32 + v_cs);
                ldsm4t(Vl4, Vl_s + (ks * 16 + v_row) * AST + nt * 32 + v_cs);
#pragma unroll
                for (int q = 0; q < 2; q++) {
                    mma16816(O[nt * 2 + q], Ph, &Vh4[q * 2]);
                    mma16816(O[nt * 2 + q], Ph, &Vl4[q * 2]);
                    mma16816(O[nt * 2 + q], Pl, &Vh4[q * 2]);
                }
            }
        }
        __syncthreads();
    }

    float inv[2] = { 1.0f / lrow[0], 1.0f / lrow[1] };
#pragma unroll
    for (int nt = 0; nt < 8; nt++) {
#pragma unroll
        for (int half = 0; half < 2; half++) {
            size_t row = qrow0 + wid * 16 + g + half * 8;
            int col = hcol + nt * 8 + t2q;
            float v0 = O[nt][half * 2] * inv[half];
            float v1 = O[nt][half * 2 + 1] * inv[half];
            bf16 h0, l0, h1, l1;
            split1(v0, h0, l0); split1(v1, h1, l1);
            *(__nv_bfloat162*)&chi[row * DD + col] = __nv_bfloat162(h0, h1);
            *(__nv_bfloat162*)&clo[row * DD + col] = __nv_bfloat162(l0, l1);
        }
    }
}

// ---------------- driver -----------------------------------------------------
extern "C" void kernel_launch(void* const* d_in, const int* in_sizes, int n_in,
                              void* d_out, int out_size) {
    (void)in_sizes; (void)n_in; (void)out_size;
    const float* tok  = (const float*)d_in[1];
    const float* pos  = (const float*)d_in[2];
    const float* bq   = (const float*)d_in[4];
    const float* bk   = (const float*)d_in[6];
    const float* bv   = (const float*)d_in[8];
    const float* bo   = (const float*)d_in[10];
    const float* b1   = (const float*)d_in[12];
    const float* b2   = (const float*)d_in[14];
    const float* ln1g = (const float*)d_in[15];
    const float* ln1b = (const float*)d_in[16];
    const float* ln2g = (const float*)d_in[17];
    const float* ln2b = (const float*)d_in[18];
    const float* lnfg = (const float*)d_in[19];
    const float* lnfb = (const float*)d_in[20];
    float* out = (float*)d_out;

    float *h;
    cudaGetSymbolAddress((void**)&h, g_h);

    bf16 *tokh, *tokl, *wqh, *wql, *wkh, *wkl, *wvh, *wvl, *woh, *wol;
    bf16 *w1h, *w1l, *w2h, *w2l, *ah, *al, *fh, *fl;
    bf16 *qh_, *ql_, *kh_, *kl_, *vh_, *vl_;
    cudaGetSymbolAddress((void**)&tokh, g_tok_hi); cudaGetSymbolAddress((void**)&tokl, g_tok_lo);
    cudaGetSymbolAddress((void**)&wqh,  g_wq_hi);  cudaGetSymbolAddress((void**)&wql,  g_wq_lo);
    cudaGetSymbolAddress((void**)&wkh,  g_wk_hi);  cudaGetSymbolAddress((void**)&wkl,  g_wk_lo);
    cudaGetSymbolAddress((void**)&wvh,  g_wv_hi);  cudaGetSymbolAddress((void**)&wvl,  g_wv_lo);
    cudaGetSymbolAddress((void**)&woh,  g_wo_hi);  cudaGetSymbolAddress((void**)&wol,  g_wo_lo);
    cudaGetSymbolAddress((void**)&w1h,  g_w1_hi);  cudaGetSymbolAddress((void**)&w1l,  g_w1_lo);
    cudaGetSymbolAddress((void**)&w2h,  g_w2_hi);  cudaGetSymbolAddress((void**)&w2l,  g_w2_lo);
    cudaGetSymbolAddress((void**)&ah,   g_a_hi);   cudaGetSymbolAddress((void**)&al,   g_a_lo);
    cudaGetSymbolAddress((void**)&fh,   g_f_hi);   cudaGetSymbolAddress((void**)&fl,   g_f_lo);
    cudaGetSymbolAddress((void**)&qh_,  g_qh);     cudaGetSymbolAddress((void**)&ql_,  g_ql);
    cudaGetSymbolAddress((void**)&kh_,  g_kh);     cudaGetSymbolAddress((void**)&kl_,  g_kl);
    cudaGetSymbolAddress((void**)&vh_,  g_vh);     cudaGetSymbolAddress((void**)&vl_,  g_vl);

    cudaFuncSetAttribute(mm_gemm128<1>, cudaFuncAttributeMaxDynamicSharedMemorySize, GSMEM128);
    cudaFuncSetAttribute(mm_gemm128<2>, cudaFuncAttributeMaxDynamicSharedMemorySize, GSMEM128);
    cudaFuncSetAttribute(mm_gemm128<3>, cudaFuncAttributeMaxDynamicSharedMemorySize, GSMEM128);
    cudaFuncSetAttribute(mm_gemm64<1>,  cudaFuncAttributeMaxDynamicSharedMemorySize, GSMEM64);
    cudaFuncSetAttribute(qkv_gemm,      cudaFuncAttributeMaxDynamicSharedMemorySize, GSMEM128);
    cudaFuncSetAttribute(flash_attn,    cudaFuncAttributeMaxDynamicSharedMemorySize, ATT_SMEM);

    // launch order chosen so ncu (-s 5 -c 1) profiles qkv_gemm (launch index 5)
    cvt_x_kernel<<<1, 256>>>((const long long*)d_in[0]);                 // 0
    embed_kernel<<<(MTOK * DD + 255) / 256, 256>>>(tok, pos);            // 1
    {
        int n4 = VV * DD / 4;
        split_kernel<<<(n4 + 255) / 256, 256>>>((const float4*)tok,      // 2
            (__nv_bfloat162*)tokh, (__nv_bfloat162*)tokl, n4);
    }
    {
        const int nD4 = LL * DD * DD / 4;     // 589824
        const int nF4 = LL * FF * DD / 4;     // 2359296
        dim3 gw((nF4 + 255) / 256, 6);
        split_w_kernel<<<gw, 256>>>(                                      // 3
            (const float4*)d_in[3],  (__nv_bfloat162*)wqh, (__nv_bfloat162*)wql, nD4,
            (const float4*)d_in[5],  (__nv_bfloat162*)wkh, (__nv_bfloat162*)wkl, nD4,
            (const float4*)d_in[7],  (__nv_bfloat162*)wvh, (__nv_bfloat162*)wvl, nD4,
            (const float4*)d_in[9],  (__nv_bfloat162*)woh, (__nv_bfloat162*)wol, nD4,
            (const float4*)d_in[11], (__nv_bfloat162*)w1h, (__nv_bfloat162*)w1l, nF4,
            (const float4*)d_in[13], (__nv_bfloat162*)w2h, (__nv_bfloat162*)w2l, nF4);
    }

    dim3 gQKV(18, MTOK / 128);
    dim3 gD64(DD / 128, MTOK / 64);    // (6, 32)
    dim3 gF(FF / 128, MTOK / 128);
    dim3 gV(VV / 128, MTOK / 128);
    dim3 gA(SS / 64, HH, BB);

    for (int l = 0; l < LL; l++) {
        const size_t wD = (size_t)l * DD * DD;
        ln_kernel<<<MTOK, 256>>>(h, ln1g + l * DD, ln1b + l * DD, ah, al);    // 4 (l=0)
        qkv_gemm<<<gQKV, 256, GSMEM128>>>(ah, al, wqh + wD, wql + wD,         // 5 (l=0)
                                          wkh + wD, wkl + wD, wvh + wD, wvl + wD,
                                          bq + l * DD, bk + l * DD, bv + l * DD,
                                          qh_, ql_, kh_, kl_, vh_, vl_);
        flash_attn<<<gA, 128, ATT_SMEM>>>(qh_, ql_, kh_, kl_, vh_, vl_, ah, al);
        mm_gemm64<1><<<gD64, 256, GSMEM64>>>(ah, al, woh + wD, wol + wD,
                                             bo + l * DD, h, h, nullptr, nullptr, DD, DD);
        ln_kernel<<<MTOK, 256>>>(h, ln2g + l * DD, ln2b + l * DD, ah, al);
        mm_gemm128<2><<<gF, 256, GSMEM128>>>(ah, al, w1h + (size_t)l * FF * DD,
                                             w1l + (size_t)l * FF * DD, b1 + l * FF,
                                             nullptr, nullptr, fh, fl, FF, DD);
        mm_gemm64<1><<<gD64, 256, GSMEM64>>>(fh, fl, w2h + (size_t)l * DD * FF,
                                             w2l + (size_t)l * DD * FF, b2 + l * DD,
                                             h, h, nullptr, nullptr, DD, FF);
    }

    ln_kernel<<<MTOK, 256>>>(h, lnfg, lnfb, ah, al);
    mm_gemm128<3><<<gV, 256, GSMEM128>>>(ah, al, tokh, tokl, nullptr, nullptr, out,
                                         nullptr, nullptr, VV, DD);
}

// round 7
// speedup vs baseline: 1.1249x; 1.1249x over previous
#include <cuda_runtime.h>
#include <cuda_bf16.h>
#include <cstdint>
#include <math.h>

#define BB 2
#define SS 1024
#define DD 768
#define HH 12
#define DK 64
#define FF 3072
#define LL 4
#define VV 32000
#define MTOK (BB*SS)   /* 2048 */

typedef __nv_bfloat16 bf16;

// ---------------- scratch ----------------------------------------------------
__device__ float g_h  [MTOK*DD];
__device__ float g_p  [3*MTOK*DD];        // split-K partials
__device__ int   g_xi [MTOK];

__device__ bf16 g_tok_hi[VV*DD],    g_tok_lo[VV*DD];
__device__ bf16 g_wq_hi [LL*DD*DD], g_wq_lo [LL*DD*DD];
__device__ bf16 g_wk_hi [LL*DD*DD], g_wk_lo [LL*DD*DD];
__device__ bf16 g_wv_hi [LL*DD*DD], g_wv_lo [LL*DD*DD];
__device__ bf16 g_wo_hi [LL*DD*DD], g_wo_lo [LL*DD*DD];
__device__ bf16 g_w1_hi [LL*FF*DD], g_w1_lo [LL*FF*DD];
__device__ bf16 g_w2_hi [LL*DD*FF], g_w2_lo [LL*DD*FF];
__device__ bf16 g_a_hi  [MTOK*DD],  g_a_lo  [MTOK*DD];
__device__ bf16 g_f_hi  [MTOK*FF],  g_f_lo  [MTOK*FF];
__device__ bf16 g_qh[MTOK*DD], g_ql[MTOK*DD];
__device__ bf16 g_kh[MTOK*DD], g_kl[MTOK*DD];
__device__ bf16 g_vh[MTOK*DD], g_vl[MTOK*DD];

// ---------------- helpers ----------------------------------------------------
__device__ __forceinline__ uint32_t smem_u32(const void* p) {
    uint32_t a;
    asm("{ .reg .u64 t; cvta.to.shared.u64 t, %1; cvt.u32.u64 %0, t; }" : "=r"(a) : "l"(p));
    return a;
}
__device__ __forceinline__ void cpasync16(uint32_t saddr, const void* gaddr) {
    asm volatile("cp.async.cg.shared.global [%0], [%1], 16;" :: "r"(saddr), "l"(gaddr));
}
#define CP_COMMIT() asm volatile("cp.async.commit_group;" ::: "memory")
#define CP_WAIT(N)  asm volatile("cp.async.wait_group %0;" :: "n"(N) : "memory")

__device__ __forceinline__ void ldsm4(uint32_t* r, uint32_t addr) {
    asm volatile("ldmatrix.sync.aligned.m8n8.x4.shared.b16 {%0,%1,%2,%3}, [%4];"
        : "=r"(r[0]), "=r"(r[1]), "=r"(r[2]), "=r"(r[3]) : "r"(addr));
}
__device__ __forceinline__ void ldsm4t(uint32_t* r, uint32_t addr) {
    asm volatile("ldmatrix.sync.aligned.m8n8.x4.trans.shared.b16 {%0,%1,%2,%3}, [%4];"
        : "=r"(r[0]), "=r"(r[1]), "=r"(r[2]), "=r"(r[3]) : "r"(addr));
}
__device__ __forceinline__ void mma16816(float* c, const uint32_t* a, const uint32_t* b) {
    asm volatile(
        "mma.sync.aligned.m16n8k16.row.col.f32.bf16.bf16.f32 "
        "{%0,%1,%2,%3}, {%4,%5,%6,%7}, {%8,%9}, {%0,%1,%2,%3};"
        : "+f"(c[0]), "+f"(c[1]), "+f"(c[2]), "+f"(c[3])
        : "r"(a[0]), "r"(a[1]), "r"(a[2]), "r"(a[3]), "r"(b[0]), "r"(b[1]));
}
__device__ __forceinline__ void split1(float v, bf16& h, bf16& l) {
    h = __float2bfloat16(v);
    l = __float2bfloat16(v - __bfloat162float(h));
}
__device__ __forceinline__ uint32_t packbf(float v0, float v1) {
    __nv_bfloat162 p(__float2bfloat16(v0), __float2bfloat16(v1));
    return *(uint32_t*)&p;
}

// ---------------- token ids / embed ------------------------------------------
__global__ void cvt_x_kernel(const long long* __restrict__ x64) {
    __shared__ int is64;
    if (threadIdx.x == 0) {
        int ok = 1;
        for (int i = 0; i < 16; i++) { long long t = x64[i]; if (t < 0 || t >= VV) ok = 0; }
        is64 = ok;
    }
    __syncthreads();
    const int* x32 = (const int*)x64;
    if (is64) for (int i = threadIdx.x; i < MTOK; i += blockDim.x) g_xi[i] = (int)x64[i];
    else      for (int i = threadIdx.x; i < MTOK; i += blockDim.x) g_xi[i] = x32[i];
}

__global__ void embed_kernel(const float* __restrict__ tok, const float* __restrict__ pos) {
    int idx = blockIdx.x * blockDim.x + threadIdx.x;
    if (idx < MTOK * DD) {
        int d = idx % DD, t = idx / DD, s = t % SS;
        g_h[idx] = tok[g_xi[t] * DD + d] + pos[s * DD + d];
    }
}

// ---------------- layernorm -> bf16 hi/lo ------------------------------------
__global__ void ln_kernel(const float* __restrict__ in, const float* __restrict__ g,
                          const float* __restrict__ b,
                          bf16* __restrict__ ohi, bf16* __restrict__ olo) {
    int row = blockIdx.x, tid = threadIdx.x;
    const float* xr = in + (size_t)row * DD;
    __shared__ float r1[256], r2[256];
    float s1 = 0.f, s2 = 0.f;
    for (int i = tid; i < DD; i += 256) { float v = xr[i]; s1 += v; s2 += v * v; }
    r1[tid] = s1; r2[tid] = s2;
    __syncthreads();
    for (int o = 128; o > 0; o >>= 1) {
        if (tid < o) { r1[tid] += r1[tid + o]; r2[tid] += r2[tid + o]; }
        __syncthreads();
    }
    float mu = r1[0] * (1.0f / DD);
    float var = r2[0] * (1.0f / DD) - mu * mu;
    float inv = rsqrtf(var + 1e-5f);
    for (int i = tid; i < DD; i += 256) {
        float v = (xr[i] - mu) * inv * g[i] + b[i];
        bf16 h, l; split1(v, h, l);
        ohi[(size_t)row * DD + i] = h;
        olo[(size_t)row * DD + i] = l;
    }
}

// fused: h += P0+P1+P2 (written back), then LN(h) -> bf16 hi/lo
__global__ void ln_res_kernel(float* __restrict__ h, const float* __restrict__ p,
                              const float* __restrict__ g, const float* __restrict__ b,
                              bf16* __restrict__ ohi, bf16* __restrict__ olo) {
    int row = blockIdx.x, tid = threadIdx.x;
    __shared__ float r1[256], r2[256];
    __shared__ float buf[DD];
    const size_t base = (size_t)row * DD;
    float s1 = 0.f, s2 = 0.f;
    for (int i = tid; i < DD; i += 256) {
        float v = h[base + i] + p[base + i] + p[(size_t)MTOK * DD + base + i]
                + p[2 * (size_t)MTOK * DD + base + i];
        h[base + i] = v;
        buf[i] = v;
        s1 += v; s2 += v * v;
    }
    r1[tid] = s1; r2[tid] = s2;
    __syncthreads();
    for (int o = 128; o > 0; o >>= 1) {
        if (tid < o) { r1[tid] += r1[tid + o]; r2[tid] += r2[tid + o]; }
        __syncthreads();
    }
    float mu = r1[0] * (1.0f / DD);
    float var = r2[0] * (1.0f / DD) - mu * mu;
    float inv = rsqrtf(var + 1e-5f);
    for (int i = tid; i < DD; i += 256) {
        float v = (buf[i] - mu) * inv * g[i] + b[i];
        bf16 hh, ll; split1(v, hh, ll);
        ohi[base + i] = hh;
        olo[base + i] = ll;
    }
}

// ---------------- fp32 -> bf16 hi/lo splits ----------------------------------
__device__ __forceinline__ void split4_body(const float4* x, __nv_bfloat162* hi,
                                            __nv_bfloat162* lo, int i) {
    float4 v = x[i];
    bf16 hx, lx, hy, ly, hz, lz, hw, lw;
    split1(v.x, hx, lx); split1(v.y, hy, ly);
    split1(v.z, hz, lz); split1(v.w, hw, lw);
    hi[2*i]   = __nv_bfloat162(hx, hy);
    hi[2*i+1] = __nv_bfloat162(hz, hw);
    lo[2*i]   = __nv_bfloat162(lx, ly);
    lo[2*i+1] = __nv_bfloat162(lz, lw);
}

__global__ void split_kernel(const float4* __restrict__ x,
                             __nv_bfloat162* __restrict__ hi,
                             __nv_bfloat162* __restrict__ lo, int n4) {
    int i = blockIdx.x * blockDim.x + threadIdx.x;
    if (i < n4) split4_body(x, hi, lo, i);
}

__global__ void split_w_kernel(
        const float4* s0, __nv_bfloat162* h0, __nv_bfloat162* l0, int n0,
        const float4* s1, __nv_bfloat162* h1, __nv_bfloat162* l1, int n1,
        const float4* s2, __nv_bfloat162* h2, __nv_bfloat162* l2, int n2,
        const float4* s3, __nv_bfloat162* h3, __nv_bfloat162* l3, int n3,
        const float4* s4, __nv_bfloat162* h4, __nv_bfloat162* l4, int n4_,
        const float4* s5, __nv_bfloat162* h5, __nv_bfloat162* l5, int n5) {
    const float4* s; __nv_bfloat162* h; __nv_bfloat162* l; int n;
    switch (blockIdx.y) {
        case 0: s = s0; h = h0; l = l0; n = n0; break;
        case 1: s = s1; h = h1; l = l1; n = n1; break;
        case 2: s = s2; h = h2; l = l2; n = n2; break;
        case 3: s = s3; h = h3; l = l3; n = n3; break;
        case 4: s = s4; h = h4; l = l4; n = n4_; break;
        default: s = s5; h = h5; l = l5; n = n5; break;
    }
    int i = blockIdx.x * blockDim.x + threadIdx.x;
    if (i < n) split4_body(s, h, l, i);
}

// ---------------- split-bf16 mma.sync GEMM core ------------------------------
#define PADE   40
#define TILEB  (128*PADE*2)
#define STB128 (4*TILEB)
#define GSMEM128 (2*STB128)             /* 81920 */

// EPI: 0 f32+optional-bias, 1 f32+bias+res, 2 bf16split+bias+relu, 3 f32,
//      4 bf16split+bias+scale
template<int EPI>
__device__ __forceinline__ void gemm_core(
        const bf16* Ahi, const bf16* Alo, const bf16* Bhi, const bf16* Blo,
        const float* bias, const float* res, float sc,
        float* C, bf16* Chi, bf16* Clo,
        int m0, int n0, int N, int K, int ldk, uint32_t sb) {
    const int tid = threadIdx.x;
    const int wid = tid >> 5, lane = tid & 31;
    const int wm = (wid >> 2) * 64;
    const int wn = (wid & 3) * 32;

    float Cf[4][4][4];
#pragma unroll
    for (int i = 0; i < 4; i++)
#pragma unroll
        for (int j = 0; j < 4; j++)
#pragma unroll
            for (int x = 0; x < 4; x++) Cf[i][j][x] = 0.f;

    const int NS = K >> 5;
    const int a_row = (lane & 15);
    const int a_colsel = (lane >> 4) * 8;
    const int b_row = (lane & 7) + ((lane >> 4) & 1) * 8;
    const int b_colsel = ((lane >> 3) & 1) * 8;
    const int lr = tid >> 2;
    const int lc = tid & 3;

#define LOAD_STAGE(SB_, K0_)                                                    \
    do {                                                                        \
        uint32_t tb = (SB_);                                                    \
        _Pragma("unroll")                                                       \
        for (int hr = 0; hr < 2; hr++) {                                        \
            int row = lr + hr * 64;                                             \
            cpasync16(tb + row * (PADE*2) + lc * 16,                            \
                      Ahi + (size_t)(m0 + row) * ldk + (K0_) + lc * 8);         \
            cpasync16(tb + TILEB + row * (PADE*2) + lc * 16,                    \
                      Alo + (size_t)(m0 + row) * ldk + (K0_) + lc * 8);         \
            cpasync16(tb + 2*TILEB + row * (PADE*2) + lc * 16,                  \
                      Bhi + (size_t)(n0 + row) * ldk + (K0_) + lc * 8);         \
            cpasync16(tb + 3*TILEB + row * (PADE*2) + lc * 16,                  \
                      Blo + (size_t)(n0 + row) * ldk + (K0_) + lc * 8);         \
        }                                                                       \
    } while (0)

    LOAD_STAGE(sb, 0);
    CP_COMMIT();

    for (int s = 0; s < NS; s++) {
        if (s + 1 < NS) {
            LOAD_STAGE(sb + ((s + 1) & 1) * STB128, (s + 1) << 5);
            CP_COMMIT();
            CP_WAIT(1);
        } else {
            CP_WAIT(0);
        }
        __syncthreads();

        const uint32_t st = sb + (s & 1) * STB128;
        const uint32_t tAh = st;
        const uint32_t tAl = st + TILEB;
        const uint32_t tBh = st + 2 * TILEB;
        const uint32_t tBl = st + 3 * TILEB;

#pragma unroll
        for (int k16 = 0; k16 < 32; k16 += 16) {
            uint32_t Aany[4][4], Bh[2][4], Bl[2][4];
#pragma unroll
            for (int mf = 0; mf < 4; mf++)
                ldsm4(Aany[mf], tAh + (wm + mf * 16 + a_row) * (PADE*2) + (k16 + a_colsel) * 2);
#pragma unroll
            for (int p = 0; p < 2; p++) {
                ldsm4(Bh[p], tBh + (wn + p * 16 + b_row) * (PADE*2) + (k16 + b_colsel) * 2);
                ldsm4(Bl[p], tBl + (wn + p * 16 + b_row) * (PADE*2) + (k16 + b_colsel) * 2);
            }
#pragma unroll
            for (int mf = 0; mf < 4; mf++)
#pragma unroll
                for (int nf = 0; nf < 4; nf++)
                    mma16816(Cf[mf][nf], Aany[mf], &Bh[nf >> 1][(nf & 1) * 2]);
#pragma unroll
            for (int mf = 0; mf < 4; mf++)
#pragma unroll
                for (int nf = 0; nf < 4; nf++)
                    mma16816(Cf[mf][nf], Aany[mf], &Bl[nf >> 1][(nf & 1) * 2]);
#pragma unroll
            for (int mf = 0; mf < 4; mf++)
                ldsm4(Aany[mf], tAl + (wm + mf * 16 + a_row) * (PADE*2) + (k16 + a_colsel) * 2);
#pragma unroll
            for (int mf = 0; mf < 4; mf++)
#pragma unroll
                for (int nf = 0; nf < 4; nf++)
                    mma16816(Cf[mf][nf], Aany[mf], &Bh[nf >> 1][(nf & 1) * 2]);
        }
        __syncthreads();
    }
#undef LOAD_STAGE

    const int g = lane >> 2, t2 = (lane & 3) * 2;
#pragma unroll
    for (int mf = 0; mf < 4; mf++) {
#pragma unroll
        for (int nf = 0; nf < 4; nf++) {
            int n = n0 + wn + nf * 8 + t2;
#pragma unroll
            for (int hrow = 0; hrow < 2; hrow++) {
                int m = m0 + wm + mf * 16 + g + hrow * 8;
                float v0 = Cf[mf][nf][hrow * 2 + 0];
                float v1 = Cf[mf][nf][hrow * 2 + 1];
                if (EPI == 0) {
                    if (bias) { v0 += bias[n]; v1 += bias[n + 1]; }
                } else if (EPI != 3) {
                    v0 += bias[n]; v1 += bias[n + 1];
                }
                if (EPI == 2 || EPI == 4) {
                    if (EPI == 2) { v0 = fmaxf(v0, 0.f); v1 = fmaxf(v1, 0.f); }
                    else          { v0 *= sc; v1 *= sc; }
                    bf16 h0, l0, h1, l1;
                    split1(v0, h0, l0); split1(v1, h1, l1);
                    *(__nv_bfloat162*)&Chi[(size_t)m * N + n] = __nv_bfloat162(h0, h1);
                    *(__nv_bfloat162*)&Clo[(size_t)m * N + n] = __nv_bfloat162(l0, l1);
                } else {
                    if (EPI == 1) {
                        const float2 rr = *(const float2*)&res[(size_t)m * N + n];
                        v0 += rr.x; v1 += rr.y;
                    }
                    *(float2*)&C[(size_t)m * N + n] = make_float2(v0, v1);
                }
            }
        }
    }
}

template<int EPI>
__global__ __launch_bounds__(256, 2)
void mm_gemm128(const bf16* __restrict__ Ahi, const bf16* __restrict__ Alo,
                const bf16* __restrict__ Bhi, const bf16* __restrict__ Blo,
                const float* __restrict__ bias, const float* __restrict__ res,
                float* __restrict__ C, bf16* __restrict__ Chi, bf16* __restrict__ Clo,
                int N, int K) {
    extern __shared__ char smem_raw[];
    gemm_core<EPI>(Ahi, Alo, Bhi, Blo, bias, res, 1.0f, C, Chi, Clo,
                   blockIdx.y * 128, blockIdx.x * 128, N, K, K, smem_u32(smem_raw));
}

// split-K partial GEMM: grid.z = K-split index; writes fp32 partials, bias at z==0
__global__ __launch_bounds__(256, 2)
void mm_gemm_pk(const bf16* __restrict__ Ahi, const bf16* __restrict__ Alo,
                const bf16* __restrict__ Bhi, const bf16* __restrict__ Blo,
                const float* __restrict__ bias, float* __restrict__ P,
                int N, int Kfull, int Ks) {
    extern __shared__ char smem_raw[];
    const int z = blockIdx.z;
    const int k0 = z * Ks;
    gemm_core<0>(Ahi + k0, Alo + k0, Bhi + k0, Blo + k0,
                 z == 0 ? bias : nullptr, nullptr, 1.0f,
                 P + (size_t)z * MTOK * N, nullptr, nullptr,
                 blockIdx.y * 128, blockIdx.x * 128, N, Ks, Kfull, smem_u32(smem_raw));
}

// fused QKV -> bf16 hi/lo outputs; q scaled by 1/8
__global__ __launch_bounds__(256, 2)
void qkv_gemm(const bf16* __restrict__ Ahi, const bf16* __restrict__ Alo,
              const bf16* __restrict__ wqh, const bf16* __restrict__ wql,
              const bf16* __restrict__ wkh, const bf16* __restrict__ wkl,
              const bf16* __restrict__ wvh, const bf16* __restrict__ wvl,
              const float* __restrict__ bq, const float* __restrict__ bk,
              const float* __restrict__ bv,
              bf16* __restrict__ qh, bf16* __restrict__ ql,
              bf16* __restrict__ kh, bf16* __restrict__ kl,
              bf16* __restrict__ vh, bf16* __restrict__ vl) {
    extern __shared__ char smem_raw[];
    const int which = blockIdx.x / 6, nb = blockIdx.x % 6;
    const bf16* Bh = (which == 0) ? wqh : (which == 1) ? wkh : wvh;
    const bf16* Bl = (which == 0) ? wql : (which == 1) ? wkl : wvl;
    const float* bias = (which == 0) ? bq : (which == 1) ? bk : bv;
    bf16* Ch = (which == 0) ? qh : (which == 1) ? kh : vh;
    bf16* Cl = (which == 0) ? ql : (which == 1) ? kl : vl;
    float sc = (which == 0) ? 0.125f : 1.0f;
    gemm_core<4>(Ahi, Alo, Bh, Bl, bias, nullptr, sc, nullptr, Ch, Cl,
                 blockIdx.y * 128, nb * 128, DD, DD, DD, smem_u32(smem_raw));
}

// ---------------- MMA flash attention ---------------------------------------
#define AST 144
#define ATILE (64*AST)
#define ATT_SMEM (2*ATILE + 2*4*ATILE)

__device__ __forceinline__ void att_load4(uint32_t dst, const bf16* src,
                                          size_t grow0, int hcol, int tid) {
    int r = tid >> 1, c0 = (tid & 1) * 4;
    const bf16* p = src + (grow0 + r) * DD + hcol + c0 * 8;
    uint32_t d = dst + r * AST + c0 * 16;
#pragma unroll
    for (int i = 0; i < 4; i++) cpasync16(d + i * 16, p + i * 8);
}

__global__ __launch_bounds__(128)
void flash_attn(const bf16* __restrict__ qh, const bf16* __restrict__ ql,
                const bf16* __restrict__ kh, const bf16* __restrict__ kl,
                const bf16* __restrict__ vh, const bf16* __restrict__ vl,
                bf16* __restrict__ chi, bf16* __restrict__ clo) {
    const int qt = gridDim.x - 1 - blockIdx.x;
    const int hd = blockIdx.y, b = blockIdx.z;
    extern __shared__ char smc[];
    const uint32_t sb = smem_u32(smc);
    const uint32_t Qh_s = sb, Ql_s = sb + ATILE;
    const uint32_t KV = sb + 2 * ATILE;

    const int tid = threadIdx.x, wid = tid >> 5, lane = tid & 31;
    const size_t qrow0 = (size_t)(b * SS + qt * 64);
    const int hcol = hd * DK;

    att_load4(Qh_s, qh, qrow0, hcol, tid);
    att_load4(Ql_s, ql, qrow0, hcol, tid);
    {
        size_t kr = (size_t)(b * SS);
        att_load4(KV + 0 * ATILE, kh, kr, hcol, tid);
        att_load4(KV + 1 * ATILE, kl, kr, hcol, tid);
        att_load4(KV + 2 * ATILE, vh, kr, hcol, tid);
        att_load4(KV + 3 * ATILE, vl, kr, hcol, tid);
    }
    CP_COMMIT();

    float O[8][4];
    float mrow[2] = { -1e30f, -1e30f };
    float lrow[2] = { 0.f, 0.f };
#pragma unroll
    for (int nt = 0; nt < 8; nt++)
#pragma unroll
        for (int x = 0; x < 4; x++) O[nt][x] = 0.f;

    const int g = lane >> 2, t2q = (lane & 3) * 2;
    const int a_row = wid * 16 + (lane & 15);
    const uint32_t a_cs = ((lane >> 4) << 3) * 2;
    const int b_row = (lane & 7) + (((lane >> 4) & 1) << 3);
    const uint32_t b_cs = (((lane >> 3) & 1) << 3) * 2;
    const int v_row = (lane & 15);
    const uint32_t v_cs = ((lane >> 4) << 3) * 2;

    for (int jt = 0; jt <= qt; jt++) {
        if (jt < qt) {
            size_t kr = (size_t)(b * SS + (jt + 1) * 64);
            uint32_t nb = KV + ((jt + 1) & 1) * (4 * ATILE);
            att_load4(nb + 0 * ATILE, kh, kr, hcol, tid);
            att_load4(nb + 1 * ATILE, kl, kr, hcol, tid);
            att_load4(nb + 2 * ATILE, vh, kr, hcol, tid);
            att_load4(nb + 3 * ATILE, vl, kr, hcol, tid);
            CP_COMMIT();
            CP_WAIT(1);
        } else {
            CP_WAIT(0);
        }
        __syncthreads();

        const uint32_t Kh_s = KV + (jt & 1) * (4 * ATILE);
        const uint32_t Kl_s = Kh_s + ATILE;
        const uint32_t Vh_s = Kl_s + ATILE;
        const uint32_t Vl_s = Vh_s + ATILE;

        float S[8][4];
#pragma unroll
        for (int nt = 0; nt < 8; nt++)
#pragma unroll
            for (int x = 0; x < 4; x++) S[nt][x] = 0.f;

#pragma unroll
        for (int ks = 0; ks < 4; ks++) {
            uint32_t Ah[4], Al[4];
            ldsm4(Ah, Qh_s + a_row * AST + ks * 32 + a_cs);
            ldsm4(Al, Ql_s + a_row * AST + ks * 32 + a_cs);
#pragma unroll
            for (int p = 0; p < 2; p++) {
                uint32_t Bh4[4], Bl4[4];
                ldsm4(Bh4, Kh_s + (p * 16 + b_row) * AST + ks * 32 + b_cs);
                ldsm4(Bl4, Kl_s + (p * 16 + b_row) * AST + ks * 32 + b_cs);
#pragma unroll
                for (int q = 0; q < 2; q++) {
                    mma16816(S[p * 2 + q], Ah, &Bh4[q * 2]);
                    mma16816(S[p * 2 + q], Ah, &Bl4[q * 2]);
                    mma16816(S[p * 2 + q], Al, &Bh4[q * 2]);
                }
                uint32_t Bh4b[4], Bl4b[4];
                ldsm4(Bh4b, Kh_s + ((p + 2) * 16 + b_row) * AST + ks * 32 + b_cs);
                ldsm4(Bl4b, Kl_s + ((p + 2) * 16 + b_row) * AST + ks * 32 + b_cs);
#pragma unroll
                for (int q = 0; q < 2; q++) {
                    mma16816(S[(p + 2) * 2 + q], Ah, &Bh4b[q * 2]);
                    mma16816(S[(p + 2) * 2 + q], Ah, &Bl4b[q * 2]);
                    mma16816(S[(p + 2) * 2 + q], Al, &Bh4b[q * 2]);
                }
            }
        }

        const bool diag = (jt == qt);
#pragma unroll
        for (int half = 0; half < 2; half++) {
            const int rloc = wid * 16 + g + half * 8;
            float mt = -1e30f;
#pragma unroll
            for (int nt = 0; nt < 8; nt++) {
                float s0 = S[nt][half * 2], s1 = S[nt][half * 2 + 1];
                if (diag) {
                    if (nt * 8 + t2q > rloc)     s0 = -1e30f;
                    if (nt * 8 + t2q + 1 > rloc) s1 = -1e30f;
                }
                S[nt][half * 2] = s0; S[nt][half * 2 + 1] = s1;
                mt = fmaxf(mt, fmaxf(s0, s1));
            }
            mt = fmaxf(mt, __shfl_xor_sync(0xffffffffu, mt, 1));
            mt = fmaxf(mt, __shfl_xor_sync(0xffffffffu, mt, 2));
            float mn = fmaxf(mrow[half], mt);
            float f = __expf(mrow[half] - mn);
            mrow[half] = mn;
            float rs = 0.f;
#pragma unroll
            for (int nt = 0; nt < 8; nt++) {
                float e0 = __expf(S[nt][half * 2] - mn);
                float e1 = __expf(S[nt][half * 2 + 1] - mn);
                S[nt][half * 2] = e0; S[nt][half * 2 + 1] = e1;
                rs += e0 + e1;
            }
            rs += __shfl_xor_sync(0xffffffffu, rs, 1);
            rs += __shfl_xor_sync(0xffffffffu, rs, 2);
            lrow[half] = lrow[half] * f + rs;
#pragma unroll
            for (int nt = 0; nt < 8; nt++) {
                O[nt][half * 2] *= f; O[nt][half * 2 + 1] *= f;
            }
        }

#pragma unroll
        for (int ks = 0; ks < 4; ks++) {
            uint32_t Ph[4], Pl[4];
#pragma unroll
            for (int q4 = 0; q4 < 4; q4++) {
                int tile = 2 * ks + (q4 >> 1);
                int o = (q4 & 1) * 2;
                float v0 = S[tile][o], v1 = S[tile][o + 1];
                bf16 h0 = __float2bfloat16(v0), h1 = __float2bfloat16(v1);
                __nv_bfloat162 hh(h0, h1);
                Ph[q4] = *(uint32_t*)&hh;
                Pl[q4] = packbf(v0 - __bfloat162float(h0), v1 - __bfloat162float(h1));
            }
#pragma unroll
            for (int nt = 0; nt < 4; nt++) {
                uint32_t Vh4[4], Vl4[4];
                ldsm4t(Vh4, Vh_s + (ks * 16 + v_row) * AST + nt * 32 + v_cs);
                ldsm4t(Vl4, Vl_s + (ks * 16 + v_row) * AST + nt * 32 + v_cs);
#pragma unroll
                for (int q = 0; q < 2; q++) {
                    mma16816(O[nt * 2 + q], Ph, &Vh4[q * 2]);
                    mma16816(O[nt * 2 + q], Ph, &Vl4[q * 2]);
                    mma16816(O[nt * 2 + q], Pl, &Vh4[q * 2]);
                }
            }
        }
        __syncthreads();
    }

    float inv[2] = { 1.0f / lrow[0], 1.0f / lrow[1] };
#pragma unroll
    for (int nt = 0; nt < 8; nt++) {
#pragma unroll
        for (int half = 0; half < 2; half++) {
            size_t row = qrow0 + wid * 16 + g + half * 8;
            int col = hcol + nt * 8 + t2q;
            float v0 = O[nt][half * 2] * inv[half];
            float v1 = O[nt][half * 2 + 1] * inv[half];
            bf16 h0, l0, h1, l1;
            split1(v0, h0, l0); split1(v1, h1, l1);
            *(__nv_bfloat162*)&chi[row * DD + col] = __nv_bfloat162(h0, h1);
            *(__nv_bfloat162*)&clo[row * DD + col] = __nv_bfloat162(l0, l1);
        }
    }
}

// ---------------- driver -----------------------------------------------------
extern "C" void kernel_launch(void* const* d_in, const int* in_sizes, int n_in,
                              void* d_out, int out_size) {
    (void)in_sizes; (void)n_in; (void)out_size;
    const float* tok  = (const float*)d_in[1];
    const float* pos  = (const float*)d_in[2];
    const float* bq   = (const float*)d_in[4];
    const float* bk   = (const float*)d_in[6];
    const float* bv   = (const float*)d_in[8];
    const float* bo   = (const float*)d_in[10];
    const float* b1   = (const float*)d_in[12];
    const float* b2   = (const float*)d_in[14];
    const float* ln1g = (const float*)d_in[15];
    const float* ln1b = (const float*)d_in[16];
    const float* ln2g = (const float*)d_in[17];
    const float* ln2b = (const float*)d_in[18];
    const float* lnfg = (const float*)d_in[19];
    const float* lnfb = (const float*)d_in[20];
    float* out = (float*)d_out;

    float *h, *pp;
    cudaGetSymbolAddress((void**)&h,  g_h);
    cudaGetSymbolAddress((void**)&pp, g_p);

    bf16 *tokh, *tokl, *wqh, *wql, *wkh, *wkl, *wvh, *wvl, *woh, *wol;
    bf16 *w1h, *w1l, *w2h, *w2l, *ah, *al, *fh, *fl;
    bf16 *qh_, *ql_, *kh_, *kl_, *vh_, *vl_;
    cudaGetSymbolAddress((void**)&tokh, g_tok_hi); cudaGetSymbolAddress((void**)&tokl, g_tok_lo);
    cudaGetSymbolAddress((void**)&wqh,  g_wq_hi);  cudaGetSymbolAddress((void**)&wql,  g_wq_lo);
    cudaGetSymbolAddress((void**)&wkh,  g_wk_hi);  cudaGetSymbolAddress((void**)&wkl,  g_wk_lo);
    cudaGetSymbolAddress((void**)&wvh,  g_wv_hi);  cudaGetSymbolAddress((void**)&wvl,  g_wv_lo);
    cudaGetSymbolAddress((void**)&woh,  g_wo_hi);  cudaGetSymbolAddress((void**)&wol,  g_wo_lo);
    cudaGetSymbolAddress((void**)&w1h,  g_w1_hi);  cudaGetSymbolAddress((void**)&w1l,  g_w1_lo);
    cudaGetSymbolAddress((void**)&w2h,  g_w2_hi);  cudaGetSymbolAddress((void**)&w2l,  g_w2_lo);
    cudaGetSymbolAddress((void**)&ah,   g_a_hi);   cudaGetSymbolAddress((void**)&al,   g_a_lo);
    cudaGetSymbolAddress((void**)&fh,   g_f_hi);   cudaGetSymbolAddress((void**)&fl,   g_f_lo);
    cudaGetSymbolAddress((void**)&qh_,  g_qh);     cudaGetSymbolAddress((void**)&ql_,  g_ql);
    cudaGetSymbolAddress((void**)&kh_,  g_kh);     cudaGetSymbolAddress((void**)&kl_,  g_kl);
    cudaGetSymbolAddress((void**)&vh_,  g_vh);     cudaGetSymbolAddress((void**)&vl_,  g_vl);

    cudaFuncSetAttribute(mm_gemm128<2>, cudaFuncAttributeMaxDynamicSharedMemorySize, GSMEM128);
    cudaFuncSetAttribute(mm_gemm128<3>, cudaFuncAttributeMaxDynamicSharedMemorySize, GSMEM128);
    cudaFuncSetAttribute(mm_gemm_pk,    cudaFuncAttributeMaxDynamicSharedMemorySize, GSMEM128);
    cudaFuncSetAttribute(qkv_gemm,      cudaFuncAttributeMaxDynamicSharedMemorySize, GSMEM128);
    cudaFuncSetAttribute(flash_attn,    cudaFuncAttributeMaxDynamicSharedMemorySize, ATT_SMEM);

    cvt_x_kernel<<<1, 256>>>((const long long*)d_in[0]);
    embed_kernel<<<(MTOK * DD + 255) / 256, 256>>>(tok, pos);
    {
        int n4 = VV * DD / 4;
        split_kernel<<<(n4 + 255) / 256, 256>>>((const float4*)tok,
            (__nv_bfloat162*)tokh, (__nv_bfloat162*)tokl, n4);
    }
    {
        const int nD4 = LL * DD * DD / 4;
        const int nF4 = LL * FF * DD / 4;
        dim3 gw((nF4 + 255) / 256, 6);
        split_w_kernel<<<gw, 256>>>(
            (const float4*)d_in[3],  (__nv_bfloat162*)wqh, (__nv_bfloat162*)wql, nD4,
            (const float4*)d_in[5],  (__nv_bfloat162*)wkh, (__nv_bfloat162*)wkl, nD4,
            (const float4*)d_in[7],  (__nv_bfloat162*)wvh, (__nv_bfloat162*)wvl, nD4,
            (const float4*)d_in[9],  (__nv_bfloat162*)woh, (__nv_bfloat162*)wol, nD4,
            (const float4*)d_in[11], (__nv_bfloat162*)w1h, (__nv_bfloat162*)w1l, nF4,
            (const float4*)d_in[13], (__nv_bfloat162*)w2h, (__nv_bfloat162*)w2l, nF4);
    }

    dim3 gQKV(18, MTOK / 128);           // (18, 16)
    dim3 gPK(DD / 128, MTOK / 128, 3);   // (6, 16, 3) — 288 CTAs
    dim3 gF(FF / 128, MTOK / 128);       // (24, 16)
    dim3 gV(VV / 128, MTOK / 128);       // (250, 16)
    dim3 gA(SS / 64, HH, BB);            // (16, 12, 2)

    for (int l = 0; l < LL; l++) {
        const size_t wD = (size_t)l * DD * DD;
        if (l == 0)
            ln_kernel<<<MTOK, 256>>>(h, ln1g, ln1b, ah, al);
        else
            ln_res_kernel<<<MTOK, 256>>>(h, pp, ln1g + l * DD, ln1b + l * DD, ah, al);
        qkv_gemm<<<gQKV, 256, GSMEM128>>>(ah, al, wqh + wD, wql + wD,
                                          wkh + wD, wkl + wD, wvh + wD, wvl + wD,
                                          bq + l * DD, bk + l * DD, bv + l * DD,
                                          qh_, ql_, kh_, kl_, vh_, vl_);
        flash_attn<<<gA, 128, ATT_SMEM>>>(qh_, ql_, kh_, kl_, vh_, vl_, ah, al);
        mm_gemm_pk<<<gPK, 256, GSMEM128>>>(ah, al, woh + wD, wol + wD,
                                           bo + l * DD, pp, DD, DD, DD / 3);
        ln_res_kernel<<<MTOK, 256>>>(h, pp, ln2g + l * DD, ln2b + l * DD, ah, al);
        mm_gemm128<2><<<gF, 256, GSMEM128>>>(ah, al, w1h + (size_t)l * FF * DD,
                                             w1l + (size_t)l * FF * DD, b1 + l * FF,
                                             nullptr, nullptr, fh, fl, FF, DD);
        mm_gemm_pk<<<gPK, 256, GSMEM128>>>(fh, fl, w2h + (size_t)l * DD * FF,
                                           w2l + (size_t)l * DD * FF, b2 + l * DD,
                                           pp, DD, FF, FF / 3);
    }

    ln_res_kernel<<<MTOK, 256>>>(h, pp, lnfg, lnfb, ah, al);
    mm_gemm128<3><<<gV, 256, GSMEM128>>>(ah, al, tokh, tokl, nullptr, nullptr, out,
                                         nullptr, nullptr, VV, DD);
}